// round 11
// baseline (speedup 1.0000x reference)
#include <cuda_runtime.h>
#include <cstdint>
#include <cstddef>

// ---------------------------------------------------------------------------
// GIN (3-layer) — Round 11.
// Gather: exact R5/R10 warp-per-node kernel (LTS-capped — frozen).
// MLP: ONE fused kernel per layer: hid=relu(A@Wa+ba) kept in smem,
//      out=hid@Wb+bb. BM=64, BN=256, 3-stage cp.async, 1 barrier/iter.
// CSR: memset + fused(count&rank + transpose) + scan + atomic-free fill.
// ---------------------------------------------------------------------------

#define N_NODES 10000
#define N_EDGES 640000
#define INC     128
#define HIDC    256

__device__ float g_agg[N_NODES * HIDC];
__device__ float g_f1 [N_NODES * HIDC];
__device__ float g_f2 [N_NODES * HIDC];
__device__ float g_wt [6 * HIDC * HIDC];
__device__ int   g_deg[N_NODES];
__device__ int   g_off[N_NODES + 1];
__device__ int   g_rank[N_EDGES];
__device__ int   g_eid[N_EDGES];

// ---------------------------------------------------------------------------
__device__ __forceinline__ uint32_t smem_u32(const void* p) {
    uint32_t a;
    asm("{ .reg .u64 t; cvta.to.shared.u64 t, %1; cvt.u32.u64 %0, t; }" : "=r"(a) : "l"(p));
    return a;
}
__device__ __forceinline__ float tf32r(float v) {
    uint32_t r;
    asm("cvt.rna.tf32.f32 %0, %1;" : "=r"(r) : "f"(v));
    return __uint_as_float(r);
}
__device__ __forceinline__ void cp16(uint32_t saddr, const void* g, int sz) {
    asm volatile("cp.async.cg.shared.global [%0], [%1], 16, %2;"
                 :: "r"(saddr), "l"(g), "r"(sz) : "memory");
}
__device__ __forceinline__ void cp_commit() {
    asm volatile("cp.async.commit_group;" ::: "memory");
}
template <int N>
__device__ __forceinline__ void cp_wait() {
    asm volatile("cp.async.wait_group %0;" :: "n"(N) : "memory");
}
__device__ __forceinline__ void mma_tf32(float* c, uint32_t a0, uint32_t a1,
                                         uint32_t a2, uint32_t a3,
                                         uint32_t b0, uint32_t b1) {
    asm volatile(
        "mma.sync.aligned.m16n8k8.row.col.f32.tf32.tf32.f32 "
        "{%0,%1,%2,%3}, {%4,%5,%6,%7}, {%8,%9}, {%0,%1,%2,%3};"
        : "+f"(c[0]), "+f"(c[1]), "+f"(c[2]), "+f"(c[3])
        : "r"(a0), "r"(a1), "r"(a2), "r"(a3), "r"(b0), "r"(b1));
}

// ---------------------------------------------------------------------------
// Fused: blocks [0, CNT_BLKS) degree count + per-edge rank; rest: transpose.
// ---------------------------------------------------------------------------
#define CNT_BLKS 625
#define TW_ELEMS (256 * INC + 5 * 256 * HIDC)
#define TW_BLKS  ((TW_ELEMS + 255) / 256)

__global__ void __launch_bounds__(256) count_and_transpose(
    const int* __restrict__ ei,
    const float* __restrict__ W0, const float* __restrict__ W1,
    const float* __restrict__ W2, const float* __restrict__ W3,
    const float* __restrict__ W4, const float* __restrict__ W5,
    float* __restrict__ wt)
{
    int b = blockIdx.x;
    if (b < CNT_BLKS) {
        int base = (b * 256 + threadIdx.x) * 4;
        if (base >= N_EDGES) return;
        int4 d = *reinterpret_cast<const int4*>(ei + N_EDGES + base);
        int r0 = atomicAdd(&g_deg[d.x], 1);
        int r1 = atomicAdd(&g_deg[d.y], 1);
        int r2 = atomicAdd(&g_deg[d.z], 1);
        int r3 = atomicAdd(&g_deg[d.w], 1);
        *reinterpret_cast<int4*>(g_rank + base) = make_int4(r0, r1, r2, r3);
    } else {
        int idx = (b - CNT_BLKS) * 256 + threadIdx.x;
        const int S0 = 256 * INC;
        const int S = 256 * HIDC;
        const float* W; int K; int loc; float* out;
        if (idx < S0) { W = W0; K = INC; loc = idx; out = wt; }
        else {
            int r = idx - S0;
            int slot = r / S; loc = r - slot * S; K = HIDC;
            if (slot >= 5) return;
            const float* Ws[5] = { W1, W2, W3, W4, W5 };
            W = Ws[slot]; out = wt + (slot + 1) * HIDC * HIDC;
        }
        int n = loc / K, k = loc - n * K;
        out[(size_t)n * K + k] = tf32r(__ldg(W + (size_t)k * 256 + n));
    }
}

__global__ void __launch_bounds__(1024) scan_kernel() {
    __shared__ int part[1024];
    const int t = threadIdx.x;
    const int CH = 10;
    int local[CH];
    int base = t * CH, s = 0;
    #pragma unroll
    for (int k = 0; k < CH; k++) {
        int idx = base + k;
        local[k] = (idx < N_NODES) ? g_deg[idx] : 0;
        s += local[k];
    }
    part[t] = s;
    __syncthreads();
    for (int d = 1; d < 1024; d <<= 1) {
        int v = (t >= d) ? part[t - d] : 0;
        __syncthreads();
        part[t] += v;
        __syncthreads();
    }
    int run = (t > 0) ? part[t - 1] : 0;
    #pragma unroll
    for (int k = 0; k < CH; k++) {
        int idx = base + k;
        if (idx < N_NODES) { g_off[idx] = run; run += local[k]; }
    }
    if (t == 1023) g_off[N_NODES] = part[1023];
}

__global__ void __launch_bounds__(256) fill_kernel(const int* __restrict__ ei) {
    int base = (blockIdx.x * blockDim.x + threadIdx.x) * 4;
    if (base >= N_EDGES) return;
    int4 s = *reinterpret_cast<const int4*>(ei + base);
    int4 d = *reinterpret_cast<const int4*>(ei + N_EDGES + base);
    int4 r = *reinterpret_cast<const int4*>(g_rank + base);
    g_eid[__ldg(g_off + d.x) + r.x] = s.x;
    g_eid[__ldg(g_off + d.y) + r.y] = s.y;
    g_eid[__ldg(g_off + d.z) + r.z] = s.z;
    g_eid[__ldg(g_off + d.w) + r.w] = s.w;
}

// ---------------------------------------------------------------------------
// gather (frozen R5 form): warp per node, 4 edges in flight.
// ---------------------------------------------------------------------------
__global__ void __launch_bounds__(256) gather_kernel(
    const float* __restrict__ feat, float* __restrict__ agg, int C4)
{
    int w = (blockIdx.x * blockDim.x + threadIdx.x) >> 5;
    if (w >= N_NODES) return;
    int lane = threadIdx.x & 31;
    int beg = __ldg(g_off + w), end = __ldg(g_off + w + 1);
    const float4* f = reinterpret_cast<const float4*>(feat);

    if (C4 == 32) {
        float4 a = __ldg(f + (size_t)w * 32 + lane);
        int j = beg;
        for (; j + 3 < end; j += 4) {
            int s0 = __ldg(g_eid + j),     s1 = __ldg(g_eid + j + 1);
            int s2 = __ldg(g_eid + j + 2), s3 = __ldg(g_eid + j + 3);
            float4 v0 = __ldg(f + (size_t)s0 * 32 + lane);
            float4 v1 = __ldg(f + (size_t)s1 * 32 + lane);
            float4 v2 = __ldg(f + (size_t)s2 * 32 + lane);
            float4 v3 = __ldg(f + (size_t)s3 * 32 + lane);
            a.x += (v0.x + v1.x) + (v2.x + v3.x);
            a.y += (v0.y + v1.y) + (v2.y + v3.y);
            a.z += (v0.z + v1.z) + (v2.z + v3.z);
            a.w += (v0.w + v1.w) + (v2.w + v3.w);
        }
        for (; j < end; j++) {
            int s0 = __ldg(g_eid + j);
            float4 v0 = __ldg(f + (size_t)s0 * 32 + lane);
            a.x += v0.x; a.y += v0.y; a.z += v0.z; a.w += v0.w;
        }
        reinterpret_cast<float4*>(agg)[(size_t)w * 32 + lane] = a;
    } else {
        float4 a0 = __ldg(f + (size_t)w * 64 + lane);
        float4 a1 = __ldg(f + (size_t)w * 64 + lane + 32);
        int j = beg;
        for (; j + 3 < end; j += 4) {
            int s0 = __ldg(g_eid + j),     s1 = __ldg(g_eid + j + 1);
            int s2 = __ldg(g_eid + j + 2), s3 = __ldg(g_eid + j + 3);
            const float4* p0 = f + (size_t)s0 * 64;
            const float4* p1 = f + (size_t)s1 * 64;
            const float4* p2 = f + (size_t)s2 * 64;
            const float4* p3 = f + (size_t)s3 * 64;
            float4 u0 = __ldg(p0 + lane), w0 = __ldg(p0 + lane + 32);
            float4 u1 = __ldg(p1 + lane), w1 = __ldg(p1 + lane + 32);
            float4 u2 = __ldg(p2 + lane), w2 = __ldg(p2 + lane + 32);
            float4 u3 = __ldg(p3 + lane), w3 = __ldg(p3 + lane + 32);
            a0.x += (u0.x + u1.x) + (u2.x + u3.x);
            a0.y += (u0.y + u1.y) + (u2.y + u3.y);
            a0.z += (u0.z + u1.z) + (u2.z + u3.z);
            a0.w += (u0.w + u1.w) + (u2.w + u3.w);
            a1.x += (w0.x + w1.x) + (w2.x + w3.x);
            a1.y += (w0.y + w1.y) + (w2.y + w3.y);
            a1.z += (w0.z + w1.z) + (w2.z + w3.z);
            a1.w += (w0.w + w1.w) + (w2.w + w3.w);
        }
        for (; j < end; j++) {
            int s0 = __ldg(g_eid + j);
            const float4* p0 = f + (size_t)s0 * 64;
            float4 u0 = __ldg(p0 + lane), w0 = __ldg(p0 + lane + 32);
            a0.x += u0.x; a0.y += u0.y; a0.z += u0.z; a0.w += u0.w;
            a1.x += w0.x; a1.y += w0.y; a1.z += w0.z; a1.w += w0.w;
        }
        reinterpret_cast<float4*>(agg)[(size_t)w * 64 + lane] = a0;
        reinterpret_cast<float4*>(agg)[(size_t)w * 64 + lane + 32] = a1;
    }
}

// ---------------------------------------------------------------------------
// Fused MLP: out[64x256] = relu?(relu(A@Wa^T + ba) @ Wb^T + bb)
// BM=64, BN=256, BK=16, 8 warps (2M x 4N), warp tile 32x64.
// Phase 1 accumulates hid in regs, stores (bias+relu+tf32) to smem;
// phase 2 streams Wb with hid as smem A operand. 3-stage pipeline.
// ---------------------------------------------------------------------------
#define BM 64
#define LDT 20
#define STAGE_F ((BM + 256) * LDT)        // 6400 floats per stage
#define A_OFF   (BM * LDT)                 // B part offset within stage
#define PIPE_F  (3 * STAGE_F)              // 19200 floats
#define LDH 260
#define HID_F   (BM * LDH)                 // 16640 floats
#define MLP_SMEM ((PIPE_F + HID_F) * 4)    // 143360 bytes

__global__ void __launch_bounds__(256) mlp_fused(
    const float* __restrict__ A,
    const float* __restrict__ Wta, const float* __restrict__ ba,
    const float* __restrict__ Wtb, const float* __restrict__ bb,
    float* __restrict__ C, int M, int K1, int relu2)
{
    extern __shared__ __align__(16) float sm[];
    float* hid = sm + PIPE_F;
    const uint32_t sbase = smem_u32(sm);

    const int tid = threadIdx.x;
    const int lane = tid & 31, wid = tid >> 5;
    const int warp_m = wid & 1, warp_n = wid >> 1;   // 2M x 4N
    const int g = lane >> 2, tig = lane & 3;
    const int mb = blockIdx.x * BM;

    const int lr  = tid >> 2;          // 0..63
    const int lc4 = tid & 3;           // 0..3

    float acc[2][8][4];
    #pragma unroll
    for (int mt = 0; mt < 2; mt++)
        #pragma unroll
        for (int nt = 0; nt < 8; nt++)
            #pragma unroll
            for (int q = 0; q < 4; q++) acc[mt][nt][q] = 0.f;

    // ---- Phase 1: hid = A @ Wa^T ------------------------------------------
    const int NC1 = K1 >> 4;

    auto issueAB = [&](int buf, int k0) {
        const uint32_t stg = sbase + buf * (STAGE_F * 4);
        {   // A: 64 rows, 1 float4/thread
            int grow = mb + lr;
            int rowc = grow < M ? grow : M - 1;
            const float* gp = A + (size_t)rowc * K1 + k0 + lc4 * 4;
            cp16(stg + (lr * LDT + lc4 * 4) * 4, gp, grow < M ? 16 : 0);
        }
        #pragma unroll
        for (int t = 0; t < 4; t++) {   // B: 256 rows, 4 float4/thread
            int r = lr + t * 64;
            const float* gp = Wta + (size_t)r * K1 + k0 + lc4 * 4;
            cp16(stg + (A_OFF + r * LDT + lc4 * 4) * 4, gp, 16);
        }
        cp_commit();
    };

    issueAB(0, 0);
    issueAB(1, 16);

    for (int i = 0; i < NC1; i++) {
        if (i + 1 < NC1) cp_wait<1>(); else cp_wait<0>();
        __syncthreads();
        if (i + 2 < NC1) issueAB((i + 2) % 3, (i + 2) << 4);

        const float* as = sm + (i % 3) * STAGE_F;
        const float* bs = as + A_OFF;

        #pragma unroll
        for (int k8 = 0; k8 < 2; k8++) {
            const int kb = k8 * 8;
            uint32_t af[2][4];
            #pragma unroll
            for (int mt = 0; mt < 2; mt++) {
                int rb = warp_m * 32 + mt * 16;
                af[mt][0] = __float_as_uint(tf32r(as[(rb + g)     * LDT + kb + tig]));
                af[mt][1] = __float_as_uint(tf32r(as[(rb + 8 + g) * LDT + kb + tig]));
                af[mt][2] = __float_as_uint(tf32r(as[(rb + g)     * LDT + kb + tig + 4]));
                af[mt][3] = __float_as_uint(tf32r(as[(rb + 8 + g) * LDT + kb + tig + 4]));
            }
            #pragma unroll
            for (int nt = 0; nt < 8; nt++) {
                int cb = warp_n * 64 + nt * 8;
                uint32_t b0 = __float_as_uint(bs[(cb + g) * LDT + kb + tig]);
                uint32_t b1 = __float_as_uint(bs[(cb + g) * LDT + kb + tig + 4]);
                #pragma unroll
                for (int mt = 0; mt < 2; mt++)
                    mma_tf32(acc[mt][nt], af[mt][0], af[mt][1], af[mt][2], af[mt][3], b0, b1);
            }
        }
    }

    // All phase-1 pipeline reads done before buffers are reused for Wb.
    __syncthreads();

    // ---- Prefetch first Wb stages -----------------------------------------
    auto issueB2 = [&](int buf, int k0) {
        const uint32_t stg = sbase + buf * (STAGE_F * 4);
        #pragma unroll
        for (int t = 0; t < 4; t++) {
            int r = lr + t * 64;
            const float* gp = Wtb + (size_t)r * 256 + k0 + lc4 * 4;
            cp16(stg + (r * LDT + lc4 * 4) * 4, gp, 16);
        }
        cp_commit();
    };
    issueB2(0, 0);
    issueB2(1, 16);

    // ---- Store hid = tf32(relu(acc + ba)) to smem; reset acc --------------
    #pragma unroll
    for (int nt = 0; nt < 8; nt++) {
        int cl = warp_n * 64 + nt * 8 + 2 * tig;
        float2 bav = __ldg(reinterpret_cast<const float2*>(ba + cl));
        #pragma unroll
        for (int mt = 0; mt < 2; mt++) {
            int r0 = warp_m * 32 + mt * 16 + g;
            float h0 = tf32r(fmaxf(acc[mt][nt][0] + bav.x, 0.f));
            float h1 = tf32r(fmaxf(acc[mt][nt][1] + bav.y, 0.f));
            float h2 = tf32r(fmaxf(acc[mt][nt][2] + bav.x, 0.f));
            float h3 = tf32r(fmaxf(acc[mt][nt][3] + bav.y, 0.f));
            *reinterpret_cast<float2*>(&hid[r0 * LDH + cl])       = make_float2(h0, h1);
            *reinterpret_cast<float2*>(&hid[(r0 + 8) * LDH + cl]) = make_float2(h2, h3);
            acc[mt][nt][0] = 0.f; acc[mt][nt][1] = 0.f;
            acc[mt][nt][2] = 0.f; acc[mt][nt][3] = 0.f;
        }
    }
    __syncthreads();

    // ---- Phase 2: out = hid @ Wb^T ----------------------------------------
    for (int i = 0; i < 16; i++) {
        if (i + 1 < 16) cp_wait<1>(); else cp_wait<0>();
        __syncthreads();
        if (i + 2 < 16) issueB2((i + 2) % 3, (i + 2) << 4);

        const float* bs = sm + (i % 3) * STAGE_F;
        const int kc0 = i << 4;

        #pragma unroll
        for (int k8 = 0; k8 < 2; k8++) {
            const int kb = k8 * 8;
            const int kc = kc0 + kb;
            uint32_t af[2][4];
            #pragma unroll
            for (int mt = 0; mt < 2; mt++) {
                int rb = warp_m * 32 + mt * 16;
                af[mt][0] = __float_as_uint(hid[(rb + g)     * LDH + kc + tig]);
                af[mt][1] = __float_as_uint(hid[(rb + 8 + g) * LDH + kc + tig]);
                af[mt][2] = __float_as_uint(hid[(rb + g)     * LDH + kc + tig + 4]);
                af[mt][3] = __float_as_uint(hid[(rb + 8 + g) * LDH + kc + tig + 4]);
            }
            #pragma unroll
            for (int nt = 0; nt < 8; nt++) {
                int cb = warp_n * 64 + nt * 8;
                uint32_t b0 = __float_as_uint(bs[(cb + g) * LDT + kb + tig]);
                uint32_t b1 = __float_as_uint(bs[(cb + g) * LDT + kb + tig + 4]);
                #pragma unroll
                for (int mt = 0; mt < 2; mt++)
                    mma_tf32(acc[mt][nt], af[mt][0], af[mt][1], af[mt][2], af[mt][3], b0, b1);
            }
        }
    }

    // ---- Epilogue: bias + optional ReLU -> global -------------------------
    #pragma unroll
    for (int nt = 0; nt < 8; nt++) {
        int col = warp_n * 64 + nt * 8 + 2 * tig;
        float2 bv = __ldg(reinterpret_cast<const float2*>(bb + col));
        #pragma unroll
        for (int mt = 0; mt < 2; mt++) {
            int row0 = mb + warp_m * 32 + mt * 16 + g;
            float2 o0 = make_float2(acc[mt][nt][0] + bv.x, acc[mt][nt][1] + bv.y);
            float2 o1 = make_float2(acc[mt][nt][2] + bv.x, acc[mt][nt][3] + bv.y);
            if (relu2) {
                o0.x = fmaxf(o0.x, 0.f); o0.y = fmaxf(o0.y, 0.f);
                o1.x = fmaxf(o1.x, 0.f); o1.y = fmaxf(o1.y, 0.f);
            }
            if (row0 < M)
                *reinterpret_cast<float2*>(C + (size_t)row0 * 256 + col) = o0;
            if (row0 + 8 < M)
                *reinterpret_cast<float2*>(C + (size_t)(row0 + 8) * 256 + col) = o1;
        }
    }
}

// ---------------------------------------------------------------------------
static void launch_layer(const float* feat, int C,
                         const float* Wta, const float* ba,
                         const float* Wtb, const float* bb,
                         float* agg, float* out, int out_relu)
{
    gather_kernel<<<(N_NODES * 32 + 255) / 256, 256>>>(feat, agg, C / 4);
    int grid = (N_NODES + BM - 1) / BM;
    mlp_fused<<<grid, 256, MLP_SMEM>>>(agg, Wta, ba, Wtb, bb, out,
                                       N_NODES, C, out_relu);
}

extern "C" void kernel_launch(void* const* d_in, const int* in_sizes, int n_in,
                              void* d_out, int out_size)
{
    const float* x  = (const float*)d_in[0];
    const int*   ei = (const int*)  d_in[1];

    cudaFuncSetAttribute(mlp_fused, cudaFuncAttributeMaxDynamicSharedMemorySize,
                         MLP_SMEM);

    float *agg, *f1, *f2, *wt;
    int* degp;
    cudaGetSymbolAddress((void**)&agg, g_agg);
    cudaGetSymbolAddress((void**)&f1,  g_f1);
    cudaGetSymbolAddress((void**)&f2,  g_f2);
    cudaGetSymbolAddress((void**)&wt,  g_wt);
    cudaGetSymbolAddress((void**)&degp, g_deg);

    cudaMemsetAsync(degp, 0, N_NODES * sizeof(int));

    count_and_transpose<<<CNT_BLKS + TW_BLKS, 256>>>(
        ei,
        (const float*)d_in[2], (const float*)d_in[4], (const float*)d_in[6],
        (const float*)d_in[8], (const float*)d_in[10], (const float*)d_in[12], wt);
    scan_kernel<<<1, 1024>>>();
    fill_kernel<<<(N_EDGES / 4 + 255) / 256, 256>>>(ei);

    float* Wt[6];
    for (int i = 0; i < 6; i++) Wt[i] = wt + i * HIDC * HIDC;
    const float* bv[6] = { (const float*)d_in[3],  (const float*)d_in[5],
                           (const float*)d_in[7],  (const float*)d_in[9],
                           (const float*)d_in[11], (const float*)d_in[13] };

    launch_layer(x,  INC,  Wt[0], bv[0], Wt[1], bv[1], agg, f1, 1);
    launch_layer(f1, HIDC, Wt[2], bv[2], Wt[3], bv[3], agg, f2, 1);
    launch_layer(f2, HIDC, Wt[4], bv[4], Wt[5], bv[5], agg, (float*)d_out, 0);
}

// round 12
// speedup vs baseline: 1.1424x; 1.1424x over previous
#include <cuda_runtime.h>
#include <cstdint>
#include <cstddef>

// ---------------------------------------------------------------------------
// GIN (3-layer) — Round 12.
// Base = R10 (best, 249.9us). One change: producer-side tf32 rounding.
//   gather stores tf32-rounded agg; GEMM epilogue rounds outputs that feed
//   downstream compute; GEMM inner loop has ZERO cvt instructions.
// Gather: R5 warp-per-node (LTS-capped — frozen).
// GEMM: BM=64/BN=128/BK=16, 3-stage cp.async, 1 barrier/iter.
// ---------------------------------------------------------------------------

#define N_NODES 10000
#define N_EDGES 640000
#define INC     128
#define HIDC    256

__device__ float g_agg[N_NODES * HIDC];
__device__ float g_hid[N_NODES * HIDC];
__device__ float g_f1 [N_NODES * HIDC];
__device__ float g_f2 [N_NODES * HIDC];
__device__ float g_wt [6 * HIDC * HIDC];
__device__ int   g_deg[N_NODES];
__device__ int   g_off[N_NODES + 1];
__device__ int   g_rank[N_EDGES];
__device__ int   g_eid[N_EDGES];

// ---------------------------------------------------------------------------
__device__ __forceinline__ uint32_t smem_u32(const void* p) {
    uint32_t a;
    asm("{ .reg .u64 t; cvta.to.shared.u64 t, %1; cvt.u32.u64 %0, t; }" : "=r"(a) : "l"(p));
    return a;
}
__device__ __forceinline__ float tf32r(float v) {
    uint32_t r;
    asm("cvt.rna.tf32.f32 %0, %1;" : "=r"(r) : "f"(v));
    return __uint_as_float(r);
}
__device__ __forceinline__ void cp16(uint32_t saddr, const void* g, int sz) {
    asm volatile("cp.async.cg.shared.global [%0], [%1], 16, %2;"
                 :: "r"(saddr), "l"(g), "r"(sz) : "memory");
}
__device__ __forceinline__ void cp_commit() {
    asm volatile("cp.async.commit_group;" ::: "memory");
}
template <int N>
__device__ __forceinline__ void cp_wait() {
    asm volatile("cp.async.wait_group %0;" :: "n"(N) : "memory");
}
__device__ __forceinline__ void mma_tf32(float* c, uint32_t a0, uint32_t a1,
                                         uint32_t a2, uint32_t a3,
                                         uint32_t b0, uint32_t b1) {
    asm volatile(
        "mma.sync.aligned.m16n8k8.row.col.f32.tf32.tf32.f32 "
        "{%0,%1,%2,%3}, {%4,%5,%6,%7}, {%8,%9}, {%0,%1,%2,%3};"
        : "+f"(c[0]), "+f"(c[1]), "+f"(c[2]), "+f"(c[3])
        : "r"(a0), "r"(a1), "r"(a2), "r"(a3), "r"(b0), "r"(b1));
}

// ---------------------------------------------------------------------------
// Fused: blocks [0, CNT_BLKS) degree count + per-edge rank; rest: transpose.
// ---------------------------------------------------------------------------
#define CNT_BLKS 625
#define TW_ELEMS (256 * INC + 5 * 256 * HIDC)
#define TW_BLKS  ((TW_ELEMS + 255) / 256)

__global__ void __launch_bounds__(256) count_and_transpose(
    const int* __restrict__ ei,
    const float* __restrict__ W0, const float* __restrict__ W1,
    const float* __restrict__ W2, const float* __restrict__ W3,
    const float* __restrict__ W4, const float* __restrict__ W5,
    float* __restrict__ wt)
{
    int b = blockIdx.x;
    if (b < CNT_BLKS) {
        int base = (b * 256 + threadIdx.x) * 4;
        if (base >= N_EDGES) return;
        int4 d = *reinterpret_cast<const int4*>(ei + N_EDGES + base);
        int r0 = atomicAdd(&g_deg[d.x], 1);
        int r1 = atomicAdd(&g_deg[d.y], 1);
        int r2 = atomicAdd(&g_deg[d.z], 1);
        int r3 = atomicAdd(&g_deg[d.w], 1);
        *reinterpret_cast<int4*>(g_rank + base) = make_int4(r0, r1, r2, r3);
    } else {
        int idx = (b - CNT_BLKS) * 256 + threadIdx.x;
        const int S0 = 256 * INC;
        const int S = 256 * HIDC;
        const float* W; int K; int loc; float* out;
        if (idx < S0) { W = W0; K = INC; loc = idx; out = wt; }
        else {
            int r = idx - S0;
            int slot = r / S; loc = r - slot * S; K = HIDC;
            if (slot >= 5) return;
            const float* Ws[5] = { W1, W2, W3, W4, W5 };
            W = Ws[slot]; out = wt + (slot + 1) * HIDC * HIDC;
        }
        int n = loc / K, k = loc - n * K;
        out[(size_t)n * K + k] = tf32r(__ldg(W + (size_t)k * 256 + n));
    }
}

__global__ void __launch_bounds__(1024) scan_kernel() {
    __shared__ int part[1024];
    const int t = threadIdx.x;
    const int CH = 10;
    int local[CH];
    int base = t * CH, s = 0;
    #pragma unroll
    for (int k = 0; k < CH; k++) {
        int idx = base + k;
        local[k] = (idx < N_NODES) ? g_deg[idx] : 0;
        s += local[k];
    }
    part[t] = s;
    __syncthreads();
    for (int d = 1; d < 1024; d <<= 1) {
        int v = (t >= d) ? part[t - d] : 0;
        __syncthreads();
        part[t] += v;
        __syncthreads();
    }
    int run = (t > 0) ? part[t - 1] : 0;
    #pragma unroll
    for (int k = 0; k < CH; k++) {
        int idx = base + k;
        if (idx < N_NODES) { g_off[idx] = run; run += local[k]; }
    }
    if (t == 1023) g_off[N_NODES] = part[1023];
}

__global__ void __launch_bounds__(256) fill_kernel(const int* __restrict__ ei) {
    int base = (blockIdx.x * blockDim.x + threadIdx.x) * 4;
    if (base >= N_EDGES) return;
    int4 s = *reinterpret_cast<const int4*>(ei + base);
    int4 d = *reinterpret_cast<const int4*>(ei + N_EDGES + base);
    int4 r = *reinterpret_cast<const int4*>(g_rank + base);
    g_eid[__ldg(g_off + d.x) + r.x] = s.x;
    g_eid[__ldg(g_off + d.y) + r.y] = s.y;
    g_eid[__ldg(g_off + d.z) + r.z] = s.z;
    g_eid[__ldg(g_off + d.w) + r.w] = s.w;
}

// ---------------------------------------------------------------------------
// gather (R5 form + tf32-rounded store): warp per node, 4 edges in flight.
// ---------------------------------------------------------------------------
__global__ void __launch_bounds__(256) gather_kernel(
    const float* __restrict__ feat, float* __restrict__ agg, int C4)
{
    int w = (blockIdx.x * blockDim.x + threadIdx.x) >> 5;
    if (w >= N_NODES) return;
    int lane = threadIdx.x & 31;
    int beg = __ldg(g_off + w), end = __ldg(g_off + w + 1);
    const float4* f = reinterpret_cast<const float4*>(feat);

    if (C4 == 32) {
        float4 a = __ldg(f + (size_t)w * 32 + lane);
        int j = beg;
        for (; j + 3 < end; j += 4) {
            int s0 = __ldg(g_eid + j),     s1 = __ldg(g_eid + j + 1);
            int s2 = __ldg(g_eid + j + 2), s3 = __ldg(g_eid + j + 3);
            float4 v0 = __ldg(f + (size_t)s0 * 32 + lane);
            float4 v1 = __ldg(f + (size_t)s1 * 32 + lane);
            float4 v2 = __ldg(f + (size_t)s2 * 32 + lane);
            float4 v3 = __ldg(f + (size_t)s3 * 32 + lane);
            a.x += (v0.x + v1.x) + (v2.x + v3.x);
            a.y += (v0.y + v1.y) + (v2.y + v3.y);
            a.z += (v0.z + v1.z) + (v2.z + v3.z);
            a.w += (v0.w + v1.w) + (v2.w + v3.w);
        }
        for (; j < end; j++) {
            int s0 = __ldg(g_eid + j);
            float4 v0 = __ldg(f + (size_t)s0 * 32 + lane);
            a.x += v0.x; a.y += v0.y; a.z += v0.z; a.w += v0.w;
        }
        a.x = tf32r(a.x); a.y = tf32r(a.y); a.z = tf32r(a.z); a.w = tf32r(a.w);
        reinterpret_cast<float4*>(agg)[(size_t)w * 32 + lane] = a;
    } else {
        float4 a0 = __ldg(f + (size_t)w * 64 + lane);
        float4 a1 = __ldg(f + (size_t)w * 64 + lane + 32);
        int j = beg;
        for (; j + 3 < end; j += 4) {
            int s0 = __ldg(g_eid + j),     s1 = __ldg(g_eid + j + 1);
            int s2 = __ldg(g_eid + j + 2), s3 = __ldg(g_eid + j + 3);
            const float4* p0 = f + (size_t)s0 * 64;
            const float4* p1 = f + (size_t)s1 * 64;
            const float4* p2 = f + (size_t)s2 * 64;
            const float4* p3 = f + (size_t)s3 * 64;
            float4 u0 = __ldg(p0 + lane), w0 = __ldg(p0 + lane + 32);
            float4 u1 = __ldg(p1 + lane), w1 = __ldg(p1 + lane + 32);
            float4 u2 = __ldg(p2 + lane), w2 = __ldg(p2 + lane + 32);
            float4 u3 = __ldg(p3 + lane), w3 = __ldg(p3 + lane + 32);
            a0.x += (u0.x + u1.x) + (u2.x + u3.x);
            a0.y += (u0.y + u1.y) + (u2.y + u3.y);
            a0.z += (u0.z + u1.z) + (u2.z + u3.z);
            a0.w += (u0.w + u1.w) + (u2.w + u3.w);
            a1.x += (w0.x + w1.x) + (w2.x + w3.x);
            a1.y += (w0.y + w1.y) + (w2.y + w3.y);
            a1.z += (w0.z + w1.z) + (w2.z + w3.z);
            a1.w += (w0.w + w1.w) + (w2.w + w3.w);
        }
        for (; j < end; j++) {
            int s0 = __ldg(g_eid + j);
            const float4* p0 = f + (size_t)s0 * 64;
            float4 u0 = __ldg(p0 + lane), w0 = __ldg(p0 + lane + 32);
            a0.x += u0.x; a0.y += u0.y; a0.z += u0.z; a0.w += u0.w;
            a1.x += w0.x; a1.y += w0.y; a1.z += w0.z; a1.w += w0.w;
        }
        a0.x = tf32r(a0.x); a0.y = tf32r(a0.y); a0.z = tf32r(a0.z); a0.w = tf32r(a0.w);
        a1.x = tf32r(a1.x); a1.y = tf32r(a1.y); a1.z = tf32r(a1.z); a1.w = tf32r(a1.w);
        reinterpret_cast<float4*>(agg)[(size_t)w * 64 + lane] = a0;
        reinterpret_cast<float4*>(agg)[(size_t)w * 64 + lane + 32] = a1;
    }
}

// ---------------------------------------------------------------------------
// GEMM: C[M,256] = A[M,K] @ Wt^T (+bias, opt ReLU, opt tf32-round of output).
// A and Wt are ALREADY tf32-rounded -> no cvt in the inner loop.
// CTA tile 64x128xK16, 8 warps (2M x 4N), 3-stage pipeline, 1 barrier/iter.
// ---------------------------------------------------------------------------
#define BM 64
#define BN 128
#define LDT 20
#define STAGE_F ((BM + BN) * LDT)
#define ATB (BM * LDT * 4)

__global__ void __launch_bounds__(256) gemm_mma(
    const float* __restrict__ A, const float* __restrict__ Bt,
    const float* __restrict__ bias, float* __restrict__ C,
    int M, int K, int relu, int rnd)
{
    __shared__ __align__(16) float sm[3 * STAGE_F];   // 46080 B
    const uint32_t sbase = smem_u32(sm);

    const int tid = threadIdx.x;
    const int lane = tid & 31, wid = tid >> 5;
    const int warp_m = wid & 1, warp_n = wid >> 1;
    const int g = lane >> 2, tig = lane & 3;
    const int nb = blockIdx.x * BN;
    const int mb = blockIdx.y * BM;

    const int lr  = tid >> 2;
    const int lc4 = tid & 3;

    float acc[2][4][4];
    #pragma unroll
    for (int mt = 0; mt < 2; mt++)
        #pragma unroll
        for (int nt = 0; nt < 4; nt++)
            #pragma unroll
            for (int q = 0; q < 4; q++) acc[mt][nt][q] = 0.f;

    const int NC = K >> 4;

    auto issue = [&](int buf, int k0) {
        const uint32_t stg = sbase + buf * (STAGE_F * 4);
        {
            int grow = mb + lr;
            int rowc = grow < M ? grow : M - 1;
            const float* gp = A + (size_t)rowc * K + k0 + lc4 * 4;
            cp16(stg + (lr * LDT + lc4 * 4) * 4, gp, grow < M ? 16 : 0);
        }
        #pragma unroll
        for (int t = 0; t < 2; t++) {
            int r = lr + t * 64;
            const float* gp = Bt + (size_t)(nb + r) * K + k0 + lc4 * 4;
            cp16(stg + ATB + (r * LDT + lc4 * 4) * 4, gp, 16);
        }
        cp_commit();
    };

    issue(0, 0);
    if (NC > 1) issue(1, 16);

    for (int i = 0; i < NC; i++) {
        if (i + 1 < NC) cp_wait<1>(); else cp_wait<0>();
        __syncthreads();
        if (i + 2 < NC) issue((i + 2) % 3, (i + 2) << 4);

        const float* as = sm + (i % 3) * STAGE_F;
        const float* bs = as + BM * LDT;

        #pragma unroll
        for (int k8 = 0; k8 < 2; k8++) {
            const int kb = k8 * 8;
            uint32_t af[2][4];
            #pragma unroll
            for (int mt = 0; mt < 2; mt++) {
                int rb = warp_m * 32 + mt * 16;
                af[mt][0] = __float_as_uint(as[(rb + g)     * LDT + kb + tig]);
                af[mt][1] = __float_as_uint(as[(rb + 8 + g) * LDT + kb + tig]);
                af[mt][2] = __float_as_uint(as[(rb + g)     * LDT + kb + tig + 4]);
                af[mt][3] = __float_as_uint(as[(rb + 8 + g) * LDT + kb + tig + 4]);
            }
            #pragma unroll
            for (int nt = 0; nt < 4; nt++) {
                int cb = warp_n * 32 + nt * 8;
                uint32_t b0 = __float_as_uint(bs[(cb + g) * LDT + kb + tig]);
                uint32_t b1 = __float_as_uint(bs[(cb + g) * LDT + kb + tig + 4]);
                #pragma unroll
                for (int mt = 0; mt < 2; mt++)
                    mma_tf32(acc[mt][nt], af[mt][0], af[mt][1], af[mt][2], af[mt][3], b0, b1);
            }
        }
    }

    #pragma unroll
    for (int nt = 0; nt < 4; nt++) {
        int col = nb + warp_n * 32 + nt * 8 + 2 * tig;
        float2 bv = __ldg(reinterpret_cast<const float2*>(bias + col));
        #pragma unroll
        for (int mt = 0; mt < 2; mt++) {
            int row0 = mb + warp_m * 32 + mt * 16 + g;
            float2 o0 = make_float2(acc[mt][nt][0] + bv.x, acc[mt][nt][1] + bv.y);
            float2 o1 = make_float2(acc[mt][nt][2] + bv.x, acc[mt][nt][3] + bv.y);
            if (relu) {
                o0.x = fmaxf(o0.x, 0.f); o0.y = fmaxf(o0.y, 0.f);
                o1.x = fmaxf(o1.x, 0.f); o1.y = fmaxf(o1.y, 0.f);
            }
            if (rnd) {
                o0.x = tf32r(o0.x); o0.y = tf32r(o0.y);
                o1.x = tf32r(o1.x); o1.y = tf32r(o1.y);
            }
            if (row0 < M)
                *reinterpret_cast<float2*>(C + (size_t)row0 * 256 + col) = o0;
            if (row0 + 8 < M)
                *reinterpret_cast<float2*>(C + (size_t)(row0 + 8) * 256 + col) = o1;
        }
    }
}

// ---------------------------------------------------------------------------
// out_rnd: layer 0/1 outputs feed the next gather/GEMM -> round; layer 2 is
// the final output -> no round, no relu.
// ---------------------------------------------------------------------------
static void launch_layer(const float* feat, int C,
                         const float* Wta, const float* ba,
                         const float* Wtb, const float* bb,
                         float* agg, float* hid, float* out,
                         int out_relu, int out_rnd)
{
    gather_kernel<<<(N_NODES * 32 + 255) / 256, 256>>>(feat, agg, C / 4);
    dim3 grid(256 / BN, (N_NODES + BM - 1) / BM);
    gemm_mma<<<grid, 256>>>(agg, Wta, ba, hid, N_NODES, C, 1, 1);
    gemm_mma<<<grid, 256>>>(hid, Wtb, bb, out, N_NODES, HIDC, out_relu, out_rnd);
}

extern "C" void kernel_launch(void* const* d_in, const int* in_sizes, int n_in,
                              void* d_out, int out_size)
{
    const float* x  = (const float*)d_in[0];
    const int*   ei = (const int*)  d_in[1];

    float *agg, *hid, *f1, *f2, *wt;
    int* degp;
    cudaGetSymbolAddress((void**)&agg, g_agg);
    cudaGetSymbolAddress((void**)&hid, g_hid);
    cudaGetSymbolAddress((void**)&f1,  g_f1);
    cudaGetSymbolAddress((void**)&f2,  g_f2);
    cudaGetSymbolAddress((void**)&wt,  g_wt);
    cudaGetSymbolAddress((void**)&degp, g_deg);

    cudaMemsetAsync(degp, 0, N_NODES * sizeof(int));

    count_and_transpose<<<CNT_BLKS + TW_BLKS, 256>>>(
        ei,
        (const float*)d_in[2], (const float*)d_in[4], (const float*)d_in[6],
        (const float*)d_in[8], (const float*)d_in[10], (const float*)d_in[12], wt);
    scan_kernel<<<1, 1024>>>();
    fill_kernel<<<(N_EDGES / 4 + 255) / 256, 256>>>(ei);

    float* Wt[6];
    for (int i = 0; i < 6; i++) Wt[i] = wt + i * HIDC * HIDC;
    const float* bv[6] = { (const float*)d_in[3],  (const float*)d_in[5],
                           (const float*)d_in[7],  (const float*)d_in[9],
                           (const float*)d_in[11], (const float*)d_in[13] };

    launch_layer(x,  INC,  Wt[0], bv[0], Wt[1], bv[1], agg, hid, f1, 1, 1);
    launch_layer(f1, HIDC, Wt[2], bv[2], Wt[3], bv[3], agg, hid, f2, 1, 1);
    launch_layer(f2, HIDC, Wt[4], bv[4], Wt[5], bv[5], agg, hid, (float*)d_out, 0, 0);
}

// round 13
// speedup vs baseline: 1.1843x; 1.0367x over previous
#include <cuda_runtime.h>
#include <cstdint>
#include <cstddef>

// ---------------------------------------------------------------------------
// GIN (3-layer) — Round 13.
// Base = R12 (best, 242.0us). One change: GEMM fragment loads via ldmatrix
// (8 LDSM.x4 per K16-iter instead of 32 LDS.32).
// Gather: R5 form + producer-side tf32 rounding (frozen).
// GEMM: BM=64/BN=128/BK=16, 3-stage cp.async, 1 barrier/iter, no inner CVT.
// ---------------------------------------------------------------------------

#define N_NODES 10000
#define N_EDGES 640000
#define INC     128
#define HIDC    256

__device__ float g_agg[N_NODES * HIDC];
__device__ float g_hid[N_NODES * HIDC];
__device__ float g_f1 [N_NODES * HIDC];
__device__ float g_f2 [N_NODES * HIDC];
__device__ float g_wt [6 * HIDC * HIDC];
__device__ int   g_deg[N_NODES];
__device__ int   g_off[N_NODES + 1];
__device__ int   g_rank[N_EDGES];
__device__ int   g_eid[N_EDGES];

// ---------------------------------------------------------------------------
__device__ __forceinline__ uint32_t smem_u32(const void* p) {
    uint32_t a;
    asm("{ .reg .u64 t; cvta.to.shared.u64 t, %1; cvt.u32.u64 %0, t; }" : "=r"(a) : "l"(p));
    return a;
}
__device__ __forceinline__ float tf32r(float v) {
    uint32_t r;
    asm("cvt.rna.tf32.f32 %0, %1;" : "=r"(r) : "f"(v));
    return __uint_as_float(r);
}
__device__ __forceinline__ void cp16(uint32_t saddr, const void* g, int sz) {
    asm volatile("cp.async.cg.shared.global [%0], [%1], 16, %2;"
                 :: "r"(saddr), "l"(g), "r"(sz) : "memory");
}
__device__ __forceinline__ void cp_commit() {
    asm volatile("cp.async.commit_group;" ::: "memory");
}
template <int N>
__device__ __forceinline__ void cp_wait() {
    asm volatile("cp.async.wait_group %0;" :: "n"(N) : "memory");
}
__device__ __forceinline__ void ldsm_x4(uint32_t& r0, uint32_t& r1,
                                        uint32_t& r2, uint32_t& r3,
                                        uint32_t addr) {
    asm volatile("ldmatrix.sync.aligned.m8n8.x4.shared.b16 {%0,%1,%2,%3}, [%4];"
                 : "=r"(r0), "=r"(r1), "=r"(r2), "=r"(r3) : "r"(addr));
}
__device__ __forceinline__ void mma_tf32(float* c, uint32_t a0, uint32_t a1,
                                         uint32_t a2, uint32_t a3,
                                         uint32_t b0, uint32_t b1) {
    asm volatile(
        "mma.sync.aligned.m16n8k8.row.col.f32.tf32.tf32.f32 "
        "{%0,%1,%2,%3}, {%4,%5,%6,%7}, {%8,%9}, {%0,%1,%2,%3};"
        : "+f"(c[0]), "+f"(c[1]), "+f"(c[2]), "+f"(c[3])
        : "r"(a0), "r"(a1), "r"(a2), "r"(a3), "r"(b0), "r"(b1));
}

// ---------------------------------------------------------------------------
// Fused: blocks [0, CNT_BLKS) degree count + per-edge rank; rest: transpose.
// ---------------------------------------------------------------------------
#define CNT_BLKS 625
#define TW_ELEMS (256 * INC + 5 * 256 * HIDC)
#define TW_BLKS  ((TW_ELEMS + 255) / 256)

__global__ void __launch_bounds__(256) count_and_transpose(
    const int* __restrict__ ei,
    const float* __restrict__ W0, const float* __restrict__ W1,
    const float* __restrict__ W2, const float* __restrict__ W3,
    const float* __restrict__ W4, const float* __restrict__ W5,
    float* __restrict__ wt)
{
    int b = blockIdx.x;
    if (b < CNT_BLKS) {
        int base = (b * 256 + threadIdx.x) * 4;
        if (base >= N_EDGES) return;
        int4 d = *reinterpret_cast<const int4*>(ei + N_EDGES + base);
        int r0 = atomicAdd(&g_deg[d.x], 1);
        int r1 = atomicAdd(&g_deg[d.y], 1);
        int r2 = atomicAdd(&g_deg[d.z], 1);
        int r3 = atomicAdd(&g_deg[d.w], 1);
        *reinterpret_cast<int4*>(g_rank + base) = make_int4(r0, r1, r2, r3);
    } else {
        int idx = (b - CNT_BLKS) * 256 + threadIdx.x;
        const int S0 = 256 * INC;
        const int S = 256 * HIDC;
        const float* W; int K; int loc; float* out;
        if (idx < S0) { W = W0; K = INC; loc = idx; out = wt; }
        else {
            int r = idx - S0;
            int slot = r / S; loc = r - slot * S; K = HIDC;
            if (slot >= 5) return;
            const float* Ws[5] = { W1, W2, W3, W4, W5 };
            W = Ws[slot]; out = wt + (slot + 1) * HIDC * HIDC;
        }
        int n = loc / K, k = loc - n * K;
        out[(size_t)n * K + k] = tf32r(__ldg(W + (size_t)k * 256 + n));
    }
}

__global__ void __launch_bounds__(1024) scan_kernel() {
    __shared__ int part[1024];
    const int t = threadIdx.x;
    const int CH = 10;
    int local[CH];
    int base = t * CH, s = 0;
    #pragma unroll
    for (int k = 0; k < CH; k++) {
        int idx = base + k;
        local[k] = (idx < N_NODES) ? g_deg[idx] : 0;
        s += local[k];
    }
    part[t] = s;
    __syncthreads();
    for (int d = 1; d < 1024; d <<= 1) {
        int v = (t >= d) ? part[t - d] : 0;
        __syncthreads();
        part[t] += v;
        __syncthreads();
    }
    int run = (t > 0) ? part[t - 1] : 0;
    #pragma unroll
    for (int k = 0; k < CH; k++) {
        int idx = base + k;
        if (idx < N_NODES) { g_off[idx] = run; run += local[k]; }
    }
    if (t == 1023) g_off[N_NODES] = part[1023];
}

__global__ void __launch_bounds__(256) fill_kernel(const int* __restrict__ ei) {
    int base = (blockIdx.x * blockDim.x + threadIdx.x) * 4;
    if (base >= N_EDGES) return;
    int4 s = *reinterpret_cast<const int4*>(ei + base);
    int4 d = *reinterpret_cast<const int4*>(ei + N_EDGES + base);
    int4 r = *reinterpret_cast<const int4*>(g_rank + base);
    g_eid[__ldg(g_off + d.x) + r.x] = s.x;
    g_eid[__ldg(g_off + d.y) + r.y] = s.y;
    g_eid[__ldg(g_off + d.z) + r.z] = s.z;
    g_eid[__ldg(g_off + d.w) + r.w] = s.w;
}

// ---------------------------------------------------------------------------
// gather (R5 form + tf32-rounded store): warp per node, 4 edges in flight.
// ---------------------------------------------------------------------------
__global__ void __launch_bounds__(256) gather_kernel(
    const float* __restrict__ feat, float* __restrict__ agg, int C4)
{
    int w = (blockIdx.x * blockDim.x + threadIdx.x) >> 5;
    if (w >= N_NODES) return;
    int lane = threadIdx.x & 31;
    int beg = __ldg(g_off + w), end = __ldg(g_off + w + 1);
    const float4* f = reinterpret_cast<const float4*>(feat);

    if (C4 == 32) {
        float4 a = __ldg(f + (size_t)w * 32 + lane);
        int j = beg;
        for (; j + 3 < end; j += 4) {
            int s0 = __ldg(g_eid + j),     s1 = __ldg(g_eid + j + 1);
            int s2 = __ldg(g_eid + j + 2), s3 = __ldg(g_eid + j + 3);
            float4 v0 = __ldg(f + (size_t)s0 * 32 + lane);
            float4 v1 = __ldg(f + (size_t)s1 * 32 + lane);
            float4 v2 = __ldg(f + (size_t)s2 * 32 + lane);
            float4 v3 = __ldg(f + (size_t)s3 * 32 + lane);
            a.x += (v0.x + v1.x) + (v2.x + v3.x);
            a.y += (v0.y + v1.y) + (v2.y + v3.y);
            a.z += (v0.z + v1.z) + (v2.z + v3.z);
            a.w += (v0.w + v1.w) + (v2.w + v3.w);
        }
        for (; j < end; j++) {
            int s0 = __ldg(g_eid + j);
            float4 v0 = __ldg(f + (size_t)s0 * 32 + lane);
            a.x += v0.x; a.y += v0.y; a.z += v0.z; a.w += v0.w;
        }
        a.x = tf32r(a.x); a.y = tf32r(a.y); a.z = tf32r(a.z); a.w = tf32r(a.w);
        reinterpret_cast<float4*>(agg)[(size_t)w * 32 + lane] = a;
    } else {
        float4 a0 = __ldg(f + (size_t)w * 64 + lane);
        float4 a1 = __ldg(f + (size_t)w * 64 + lane + 32);
        int j = beg;
        for (; j + 3 < end; j += 4) {
            int s0 = __ldg(g_eid + j),     s1 = __ldg(g_eid + j + 1);
            int s2 = __ldg(g_eid + j + 2), s3 = __ldg(g_eid + j + 3);
            const float4* p0 = f + (size_t)s0 * 64;
            const float4* p1 = f + (size_t)s1 * 64;
            const float4* p2 = f + (size_t)s2 * 64;
            const float4* p3 = f + (size_t)s3 * 64;
            float4 u0 = __ldg(p0 + lane), w0 = __ldg(p0 + lane + 32);
            float4 u1 = __ldg(p1 + lane), w1 = __ldg(p1 + lane + 32);
            float4 u2 = __ldg(p2 + lane), w2 = __ldg(p2 + lane + 32);
            float4 u3 = __ldg(p3 + lane), w3 = __ldg(p3 + lane + 32);
            a0.x += (u0.x + u1.x) + (u2.x + u3.x);
            a0.y += (u0.y + u1.y) + (u2.y + u3.y);
            a0.z += (u0.z + u1.z) + (u2.z + u3.z);
            a0.w += (u0.w + u1.w) + (u2.w + u3.w);
            a1.x += (w0.x + w1.x) + (w2.x + w3.x);
            a1.y += (w0.y + w1.y) + (w2.y + w3.y);
            a1.z += (w0.z + w1.z) + (w2.z + w3.z);
            a1.w += (w0.w + w1.w) + (w2.w + w3.w);
        }
        for (; j < end; j++) {
            int s0 = __ldg(g_eid + j);
            const float4* p0 = f + (size_t)s0 * 64;
            float4 u0 = __ldg(p0 + lane), w0 = __ldg(p0 + lane + 32);
            a0.x += u0.x; a0.y += u0.y; a0.z += u0.z; a0.w += u0.w;
            a1.x += w0.x; a1.y += w0.y; a1.z += w0.z; a1.w += w0.w;
        }
        a0.x = tf32r(a0.x); a0.y = tf32r(a0.y); a0.z = tf32r(a0.z); a0.w = tf32r(a0.w);
        a1.x = tf32r(a1.x); a1.y = tf32r(a1.y); a1.z = tf32r(a1.z); a1.w = tf32r(a1.w);
        reinterpret_cast<float4*>(agg)[(size_t)w * 64 + lane] = a0;
        reinterpret_cast<float4*>(agg)[(size_t)w * 64 + lane + 32] = a1;
    }
}

// ---------------------------------------------------------------------------
// GEMM: C[M,256] = A[M,K] @ Wt^T (+bias, opt ReLU, opt tf32-round).
// Operands pre-rounded; fragment loads via ldmatrix.x4 (conflict-free with
// LDT=20). CTA 64x128xK16, 8 warps (2M x 4N), 3-stage pipeline.
// ---------------------------------------------------------------------------
#define BM 64
#define BN 128
#define LDT 20
#define STAGE_F ((BM + BN) * LDT)
#define STAGE_B (STAGE_F * 4)
#define ATB (BM * LDT * 4)

__global__ void __launch_bounds__(256) gemm_mma(
    const float* __restrict__ A, const float* __restrict__ Bt,
    const float* __restrict__ bias, float* __restrict__ C,
    int M, int K, int relu, int rnd)
{
    __shared__ __align__(16) float sm[3 * STAGE_F];   // 46080 B
    const uint32_t sbase = smem_u32(sm);

    const int tid = threadIdx.x;
    const int lane = tid & 31, wid = tid >> 5;
    const int warp_m = wid & 1, warp_n = wid >> 1;
    const int g = lane >> 2, tig = lane & 3;
    const int nb = blockIdx.x * BN;
    const int mb = blockIdx.y * BM;

    const int lr  = tid >> 2;
    const int lc4 = tid & 3;

    // ldmatrix per-lane offsets (bytes within a stage).
    // Tile q = lane>>3, row-in-tile rr = lane&7.
    const int q  = lane >> 3;
    const int rr = lane & 7;
    // A fragments: offA[mt][k8]; rows warp_m*32 + mt*16 + (q&1)*8 + rr,
    //              cols k8*8 + (q>>1)*4.
    uint32_t offA[2][2], offB[2][2];
    #pragma unroll
    for (int mt = 0; mt < 2; mt++)
        #pragma unroll
        for (int k8 = 0; k8 < 2; k8++)
            offA[mt][k8] = ((warp_m * 32 + mt * 16 + (q & 1) * 8 + rr) * LDT
                            + k8 * 8 + (q >> 1) * 4) * 4;
    // B fragments: pair np covers nt=2np,2np+1; rows warp_n*32 + np*16 +
    //              (q>>1)*8 + rr, cols k8*8 + (q&1)*4. Regs: r0,r1 = b0,b1 of
    //              nt=2np; r2,r3 = b0,b1 of nt=2np+1.
    #pragma unroll
    for (int np = 0; np < 2; np++)
        #pragma unroll
        for (int k8 = 0; k8 < 2; k8++)
            offB[np][k8] = ATB + ((warp_n * 32 + np * 16 + (q >> 1) * 8 + rr) * LDT
                                  + k8 * 8 + (q & 1) * 4) * 4;

    float acc[2][4][4];
    #pragma unroll
    for (int mt = 0; mt < 2; mt++)
        #pragma unroll
        for (int nt = 0; nt < 4; nt++)
            #pragma unroll
            for (int qq = 0; qq < 4; qq++) acc[mt][nt][qq] = 0.f;

    const int NC = K >> 4;

    auto issue = [&](int buf, int k0) {
        const uint32_t stg = sbase + buf * STAGE_B;
        {
            int grow = mb + lr;
            int rowc = grow < M ? grow : M - 1;
            const float* gp = A + (size_t)rowc * K + k0 + lc4 * 4;
            cp16(stg + (lr * LDT + lc4 * 4) * 4, gp, grow < M ? 16 : 0);
        }
        #pragma unroll
        for (int t = 0; t < 2; t++) {
            int r = lr + t * 64;
            const float* gp = Bt + (size_t)(nb + r) * K + k0 + lc4 * 4;
            cp16(stg + ATB + (r * LDT + lc4 * 4) * 4, gp, 16);
        }
        cp_commit();
    };

    issue(0, 0);
    if (NC > 1) issue(1, 16);

    for (int i = 0; i < NC; i++) {
        if (i + 1 < NC) cp_wait<1>(); else cp_wait<0>();
        __syncthreads();
        if (i + 2 < NC) issue((i + 2) % 3, (i + 2) << 4);

        const uint32_t stg = sbase + (i % 3) * STAGE_B;

        #pragma unroll
        for (int k8 = 0; k8 < 2; k8++) {
            uint32_t af[2][4], bf[2][4];
            ldsm_x4(af[0][0], af[0][1], af[0][2], af[0][3], stg + offA[0][k8]);
            ldsm_x4(af[1][0], af[1][1], af[1][2], af[1][3], stg + offA[1][k8]);
            ldsm_x4(bf[0][0], bf[0][1], bf[0][2], bf[0][3], stg + offB[0][k8]);
            ldsm_x4(bf[1][0], bf[1][1], bf[1][2], bf[1][3], stg + offB[1][k8]);
            #pragma unroll
            for (int nt = 0; nt < 4; nt++) {
                uint32_t b0 = bf[nt >> 1][(nt & 1) * 2];
                uint32_t b1 = bf[nt >> 1][(nt & 1) * 2 + 1];
                #pragma unroll
                for (int mt = 0; mt < 2; mt++)
                    mma_tf32(acc[mt][nt], af[mt][0], af[mt][1], af[mt][2], af[mt][3], b0, b1);
            }
        }
    }

    #pragma unroll
    for (int nt = 0; nt < 4; nt++) {
        int col = nb + warp_n * 32 + nt * 8 + 2 * tig;
        float2 bv = __ldg(reinterpret_cast<const float2*>(bias + col));
        #pragma unroll
        for (int mt = 0; mt < 2; mt++) {
            int row0 = mb + warp_m * 32 + mt * 16 + g;
            float2 o0 = make_float2(acc[mt][nt][0] + bv.x, acc[mt][nt][1] + bv.y);
            float2 o1 = make_float2(acc[mt][nt][2] + bv.x, acc[mt][nt][3] + bv.y);
            if (relu) {
                o0.x = fmaxf(o0.x, 0.f); o0.y = fmaxf(o0.y, 0.f);
                o1.x = fmaxf(o1.x, 0.f); o1.y = fmaxf(o1.y, 0.f);
            }
            if (rnd) {
                o0.x = tf32r(o0.x); o0.y = tf32r(o0.y);
                o1.x = tf32r(o1.x); o1.y = tf32r(o1.y);
            }
            if (row0 < M)
                *reinterpret_cast<float2*>(C + (size_t)row0 * 256 + col) = o0;
            if (row0 + 8 < M)
                *reinterpret_cast<float2*>(C + (size_t)(row0 + 8) * 256 + col) = o1;
        }
    }
}

// ---------------------------------------------------------------------------
static void launch_layer(const float* feat, int C,
                         const float* Wta, const float* ba,
                         const float* Wtb, const float* bb,
                         float* agg, float* hid, float* out,
                         int out_relu, int out_rnd)
{
    gather_kernel<<<(N_NODES * 32 + 255) / 256, 256>>>(feat, agg, C / 4);
    dim3 grid(256 / BN, (N_NODES + BM - 1) / BM);
    gemm_mma<<<grid, 256>>>(agg, Wta, ba, hid, N_NODES, C, 1, 1);
    gemm_mma<<<grid, 256>>>(hid, Wtb, bb, out, N_NODES, HIDC, out_relu, out_rnd);
}

extern "C" void kernel_launch(void* const* d_in, const int* in_sizes, int n_in,
                              void* d_out, int out_size)
{
    const float* x  = (const float*)d_in[0];
    const int*   ei = (const int*)  d_in[1];

    float *agg, *hid, *f1, *f2, *wt;
    int* degp;
    cudaGetSymbolAddress((void**)&agg, g_agg);
    cudaGetSymbolAddress((void**)&hid, g_hid);
    cudaGetSymbolAddress((void**)&f1,  g_f1);
    cudaGetSymbolAddress((void**)&f2,  g_f2);
    cudaGetSymbolAddress((void**)&wt,  g_wt);
    cudaGetSymbolAddress((void**)&degp, g_deg);

    cudaMemsetAsync(degp, 0, N_NODES * sizeof(int));

    count_and_transpose<<<CNT_BLKS + TW_BLKS, 256>>>(
        ei,
        (const float*)d_in[2], (const float*)d_in[4], (const float*)d_in[6],
        (const float*)d_in[8], (const float*)d_in[10], (const float*)d_in[12], wt);
    scan_kernel<<<1, 1024>>>();
    fill_kernel<<<(N_EDGES / 4 + 255) / 256, 256>>>(ei);

    float* Wt[6];
    for (int i = 0; i < 6; i++) Wt[i] = wt + i * HIDC * HIDC;
    const float* bv[6] = { (const float*)d_in[3],  (const float*)d_in[5],
                           (const float*)d_in[7],  (const float*)d_in[9],
                           (const float*)d_in[11], (const float*)d_in[13] };

    launch_layer(x,  INC,  Wt[0], bv[0], Wt[1], bv[1], agg, hid, f1, 1, 1);
    launch_layer(f1, HIDC, Wt[2], bv[2], Wt[3], bv[3], agg, hid, f2, 1, 1);
    launch_layer(f2, HIDC, Wt[4], bv[4], Wt[5], bv[5], agg, hid, (float*)d_out, 0, 0);
}